// round 16
// baseline (speedup 1.0000x reference)
#include <cuda_runtime.h>
#include <math.h>

// x: [B=256, K=1048576]; memory: [E=8, K]
#define BN   256
#define EN   8
#define KN   1048576
#define K4N  (KN / 4)
#define CK   512             // chunk size in floats (k per block)
#define CK4  (CK / 4)        // 128
#define NCH  (KN / CK)       // 2048 chunks
#define KS   16              // k-slice staged in smem per warp step (1 KB)
#define NSL  (CK / KS)       // 32 slices per chunk
#define XSTR 20              // x_s row stride: 20g%32 distinct, no wrap (see proof)
#define MSTR 516             // m_s row stride: 516 % 32 == 4
#define XBUF (16 * XSTR)     // one slice buffer (floats) per warp = 320
#define DSMEM ((8 * MSTR + 8 * 2 * XBUF) * 4)   // 36992 B -> 6 blocks/SM, 48 warps

// Scratch (device globals -- no allocation allowed).
// g_dotp layout: [c][b][e] -- sector (32B) = one (c,b) pair, written entirely
// by one warp epilogue; k_argmax block b consumes b's sectors whole.
__device__ float g_dotp[(size_t)NCH * BN * EN];  // 16.8 MB
__device__ float g_mpart[EN * NCH];
__device__ int   g_experts[BN];

__device__ __forceinline__ float warp_sum(float v) {
    #pragma unroll
    for (int o = 16; o; o >>= 1)
        v += __shfl_xor_sync(0xffffffffu, v, o);
    return v;
}

// tf32 m16n8k8 MMA: D += A(16x8) * B(8x8) (fp32 bits reinterpreted as tf32).
__device__ __forceinline__ void mma_tf32(float acc[4],
                                         float a0, float a1, float a2, float a3,
                                         float b0, float b1) {
    asm volatile(
        "mma.sync.aligned.m16n8k8.row.col.f32.tf32.tf32.f32 "
        "{%0,%1,%2,%3}, {%4,%5,%6,%7}, {%8,%9}, {%0,%1,%2,%3};\n"
        : "+f"(acc[0]), "+f"(acc[1]), "+f"(acc[2]), "+f"(acc[3])
        : "r"(__float_as_uint(a0)), "r"(__float_as_uint(a1)),
          "r"(__float_as_uint(a2)), "r"(__float_as_uint(a3)),
          "r"(__float_as_uint(b0)), "r"(__float_as_uint(b1)));
}

// 16B async copy gmem -> smem, L2-only (streaming x).
__device__ __forceinline__ void cpa16(unsigned dst, const void* src) {
    asm volatile("cp.async.cg.shared.global [%0], [%1], 16;\n"
                 :: "r"(dst), "l"(src));
}

// ---------------------------------------------------------------------------
// Pass 1: tensor-core dot partials. Block: 8 warps, 128 b-rows (16/warp),
// one k-chunk of 512 in 32 slices of 16 cols (1 KB). Double-buffered
// cp.async; 37.0 KB smem -> 6 blocks/SM = 48 warps (vs 32 before) for a
// deeper per-SM memory queue. Slice-0 cp.asyncs issued before m staging.
// Bank proofs: STS quarter-warp (q fixed): banks 20*r0%32 = {0,20,8,28,16,
// 4,24,12} distinct. A-loads: (20g + k + tg)%32 distinct, no wrap, for
// k in {0,4,8,12}. B-loads: 516g%32 = 4g -> distinct.
// ---------------------------------------------------------------------------
__global__ void __launch_bounds__(256) k_dots(const float* __restrict__ x,
                                              const float* __restrict__ mem)
{
    extern __shared__ float smem_[];
    float* m_s = smem_;                        // 8 * 516 floats
    float* x_s = smem_ + 8 * MSTR;             // 8 warps * 2 * 320 floats

    const int c   = blockIdx.x;                // chunk
    const int bt  = blockIdx.y;                // b tile (0..1), 128 b each
    const int tid = threadIdx.x;
    const int w   = tid >> 5;
    const int l   = tid & 31;
    const int g   = l >> 2;                    // 0..7  (mma groupID)
    const int tg  = l & 3;                     // 0..3
    const int r0  = l & 7;                     // 0..7  (staging row)
    const int q   = l >> 3;                    // 0..3  (staging float4 col)

    const int b0row = bt * 128 + w * 16;
    // lane stages rows r0 and r0+8 (ops 0/1), float4-col q of each slice
    const float4* xb = (const float4*)x
                     + (size_t)(b0row + r0) * K4N + (size_t)c * CK4 + q;

    float* xw_base = x_s + w * (2 * XBUF);
    const unsigned xs_t = (unsigned)__cvta_generic_to_shared(xw_base)
                        + (unsigned)((r0 * XSTR + 4 * q) * 4);

    // ---- issue x slice-0 BEFORE m staging (overlap) ----
    cpa16(xs_t,                                xb);
    cpa16(xs_t + (unsigned)(8 * XSTR * 4),     xb + (size_t)8 * K4N);
    asm volatile("cp.async.commit_group;\n" ::: "memory");

    // ---- stage m chunk: 1024 float4 / 256 threads = 4 each (coalesced) ----
    const float4* m4 = (const float4*)mem;
    #pragma unroll
    for (int i = 0; i < 4; ++i) {
        int slot = tid + 256 * i;              // 0..1023
        int e = slot >> 7;                     // /128
        int qq = slot & 127;
        float4 v = m4[(size_t)e * K4N + (size_t)c * CK4 + qq];
        *(float4*)&m_s[e * MSTR + 4 * qq] = v;
    }
    __syncthreads();

    // ---- ||m_e||^2 chunk partials (one b-tile only; warp w == expert w) ----
    if (bt == 0) {
        float s = 0.f;
        #pragma unroll
        for (int j = 0; j < 4; ++j) {
            float4 f = *(const float4*)&m_s[w * MSTR + 4 * (l + 32 * j)];
            s += f.x * f.x + f.y * f.y + f.z * f.z + f.w * f.w;
        }
        s = warp_sum(s);
        if (l == 0) g_mpart[w * NCH + c] = s;
    }

    float acc[4] = {0.f, 0.f, 0.f, 0.f};

    #pragma unroll 1
    for (int s = 0; s < NSL; ++s) {
        if (s + 1 < NSL) {
            const unsigned nb = (unsigned)(((s + 1) & 1) * XBUF * 4);
            cpa16(xs_t + nb,
                  xb + (size_t)(s + 1) * 4);
            cpa16(xs_t + nb + (unsigned)(8 * XSTR * 4),
                  xb + (size_t)8 * K4N + (size_t)(s + 1) * 4);
            asm volatile("cp.async.commit_group;\n" ::: "memory");
            asm volatile("cp.async.wait_group 1;\n" ::: "memory");
        } else {
            asm volatile("cp.async.wait_group 0;\n" ::: "memory");
        }
        __syncwarp();

        const float* xw = xw_base + (s & 1) * XBUF;
        const int cbase = s * KS;
        #pragma unroll
        for (int k8 = 0; k8 < KS / 8; ++k8) {
            const int k = k8 * 8;
            // A fragments (row-major 16x8): rows g, g+8; cols k+tg, k+4+tg
            float a0 = xw[g       * XSTR + k + tg];
            float a1 = xw[(g + 8) * XSTR + k + tg];
            float a2 = xw[g       * XSTR + k + 4 + tg];
            float a3 = xw[(g + 8) * XSTR + k + 4 + tg];
            // B fragments (col-major 8x8): B[k][n] = m[n][k]; n = g
            float b0 = m_s[g * MSTR + cbase + k + tg];
            float b1 = m_s[g * MSTR + cbase + k + 4 + tg];

            mma_tf32(acc, a0, a1, a2, a3, b0, b1);
        }
        __syncwarp();   // all lanes done reading buffer s&1 before refill
    }

    // ---- write dot partials, layout [c][b][e]: float2 stores ----
    const size_t cb = (size_t)c * BN;
    *(float2*)&g_dotp[(cb + b0row + g)     * EN + 2 * tg]
        = make_float2(acc[0], acc[1]);
    *(float2*)&g_dotp[(cb + b0row + g + 8) * EN + 2 * tg]
        = make_float2(acc[2], acc[3]);
}

// ---------------------------------------------------------------------------
// Pass 2: one block per b. Thread tid = (cres, e), e = tid&7, cres = tid>>3:
// accumulates dot[b][e] over chunks c = i*32 + cres. Lanes 8t..8t+7 read one
// whole 32B sector; unroll 16 for MLP. Deterministic fixed-order sums.
// ---------------------------------------------------------------------------
__global__ void __launch_bounds__(256) k_argmax(float* __restrict__ outExp)
{
    const int b   = blockIdx.x;
    const int tid = threadIdx.x;
    const int w   = tid >> 5;
    const int l   = tid & 31;
    const int e   = tid & 7;
    const int cr  = tid >> 3;      // 0..31

    __shared__ float red[256];
    __shared__ float smn[EN];

    // ---- dot partial accumulation over c = i*32 + cr ----
    {
        const float* p = g_dotp + (size_t)b * EN + e;
        float acc = 0.f;
        #pragma unroll 16
        for (int i = 0; i < NCH / 32; ++i)
            acc += p[(size_t)(i * 32 + cr) * (BN * EN)];
        red[tid] = acc;
    }
    // ---- ||m_e||^2: warp w reduces expert w's chunk partials ----
    {
        const float* p = g_mpart + (size_t)w * NCH;
        float v = 0.f;
        #pragma unroll
        for (int g = 0; g < NCH / 32; ++g) v += p[g * 32 + l];
        v = warp_sum(v);
        if (l == 0) smn[w] = v;
    }
    __syncthreads();

    if (tid == 0) {
        float best = -3.4e38f;
        int   bi   = 0;
        #pragma unroll
        for (int ee = 0; ee < EN; ++ee) {
            float v = 0.f;
            #pragma unroll
            for (int j = 0; j < 32; ++j) v += red[j * 8 + ee];
            float s = v / sqrtf(smn[ee]);
            if (s > best) { best = s; bi = ee; }  // first-max (jnp.argmax)
        }
        g_experts[b] = bi;
        if (outExp) outExp[b] = (float)bi;
    }
}

// ---------------------------------------------------------------------------
// Pass 3: scatter-mean update with integrated ballot counting-sort prologue
// (every block recomputes the stable order from g_experts; deterministic).
// ---------------------------------------------------------------------------
__global__ void __launch_bounds__(256) k_update(const float* __restrict__ x,
                                                const float* __restrict__ mem,
                                                float* __restrict__ outMem)
{
    __shared__ int   s_order[BN];
    __shared__ int   s_offs[EN + 1];
    __shared__ float s_ka[EN];
    __shared__ float s_kb[EN];
    __shared__ int   wcnt[8][EN];

    const int tid = threadIdx.x;       // tid == b for the sort prologue
    const int w = tid >> 5, l = tid & 31;

    // ---- stable counting sort by expert (ballot ranking) ----
    if (tid < 8 * EN) ((int*)wcnt)[tid] = 0;
    __syncthreads();

    const int e = g_experts[tid];
    unsigned mk = __match_any_sync(0xffffffffu, e);
    int lower = __popc(mk & ((1u << l) - 1u));
    if (lower == 0) wcnt[w][e] = __popc(mk);
    __syncthreads();

    if (tid < EN) {
        int t = 0;
        #pragma unroll
        for (int ww = 0; ww < 8; ++ww) t += wcnt[ww][tid];
        s_offs[tid + 1] = t;
        if (t > 0) { s_ka[tid] = 0.5f; s_kb[tid] = 0.5f / (float)t; }
        else       { s_ka[tid] = 1.0f; s_kb[tid] = 0.0f; }
    }
    __syncthreads();
    if (tid == 0) {
        s_offs[0] = 0;
        #pragma unroll
        for (int i = 0; i < EN; ++i) s_offs[i + 1] += s_offs[i];
    }
    __syncthreads();

    {
        int rank = lower;
        #pragma unroll
        for (int ww = 0; ww < 8; ++ww)
            if (ww < w) rank += wcnt[ww][e];
        s_order[s_offs[e] + rank] = tid;
    }
    __syncthreads();

    // ---- streaming update ----
    const size_t j4 = (size_t)blockIdx.x * 256 + tid;
    const float4* x4 = (const float4*)x;
    const float4* m4 = (const float4*)mem;
    float4*       o4 = (float4*)outMem;

    #pragma unroll 1
    for (int ee = 0; ee < EN; ++ee) {
        float ax = 0.f, ay = 0.f, az = 0.f, aw = 0.f;
        const int lo = s_offs[ee];
        const int hi = s_offs[ee + 1];
        #pragma unroll 4
        for (int i = lo; i < hi; ++i) {
            int b = s_order[i];
            float4 f = x4[(size_t)b * K4N + j4];
            ax += f.x; ay += f.y; az += f.z; aw += f.w;
        }
        const float ka = s_ka[ee];
        const float kb = s_kb[ee];
        float4 mv = m4[(size_t)ee * K4N + j4];
        float4 ov;
        ov.x = ka * mv.x + kb * ax;
        ov.y = ka * mv.y + kb * ay;
        ov.z = ka * mv.z + kb * az;
        ov.w = ka * mv.w + kb * aw;
        o4[(size_t)ee * K4N + j4] = ov;
    }
}

// ---------------------------------------------------------------------------
extern "C" void kernel_launch(void* const* d_in, const int* in_sizes, int n_in,
                              void* d_out, int out_size)
{
    const float* x   = (const float*)d_in[0];
    const float* mem = (const float*)d_in[1];
    float* out = (float*)d_out;

    const long memElems = (long)EN * KN;          // 8388608
    float* outExp = nullptr;
    float* outMem = nullptr;
    if ((long)out_size == memElems + BN) {        // concat: experts then new_memory
        outExp = out;
        outMem = out + BN;
    } else if ((long)out_size == memElems) {      // new_memory only
        outMem = out;
    } else {                                      // experts only (fallback)
        outExp = out;
    }

    cudaFuncSetAttribute(k_dots, cudaFuncAttributeMaxDynamicSharedMemorySize, DSMEM);

    dim3 g1(NCH, 2);
    k_dots<<<g1, 256, DSMEM>>>(x, mem);
    k_argmax<<<BN, 256>>>(outExp);
    if (outMem) k_update<<<K4N / 256, 256>>>(x, mem, outMem);
}

// round 17
// speedup vs baseline: 1.4779x; 1.4779x over previous
#include <cuda_runtime.h>
#include <math.h>

// x: [B=256, K=1048576]; memory: [E=8, K]
#define BN   256
#define EN   8
#define KN   1048576
#define K4N  (KN / 4)
#define CK   512             // chunk size in floats (k per block)
#define CK4  (CK / 4)        // 128
#define NCH  (KN / CK)       // 2048 chunks
#define KS   32              // k-slice staged in smem per warp step (2 KB)
#define NSL  (CK / KS)       // 16 slices per chunk
#define XSTR 36              // x_s row stride (floats): 4g+tg distinct mod 32
#define MSTR 516             // m_s row stride (floats): 516 % 32 == 4
#define XBUF (16 * XSTR)     // one slice buffer (floats) per warp = 576
#define NW   16              // warps per k_dots block (512 threads, all 256 b)
#define DSMEM ((8 * MSTR + NW * 2 * XBUF) * 4)   // 90240 B -> 2 blocks/SM

// Scratch (device globals -- no allocation allowed).
// g_dotp layout: [b][c][e] -- writer fills whole 32B sectors (no
// amplification); reader (argmax block b) streams 64 KB contiguously.
__device__ float g_dotp[(size_t)BN * NCH * EN];  // 16.8 MB
__device__ float g_mpart[EN * NCH];
__device__ int   g_experts[BN];

__device__ __forceinline__ float warp_sum(float v) {
    #pragma unroll
    for (int o = 16; o; o >>= 1)
        v += __shfl_xor_sync(0xffffffffu, v, o);
    return v;
}

// tf32 m16n8k8 MMA: D += A(16x8) * B(8x8) (fp32 bits reinterpreted as tf32).
__device__ __forceinline__ void mma_tf32(float acc[4],
                                         float a0, float a1, float a2, float a3,
                                         float b0, float b1) {
    asm volatile(
        "mma.sync.aligned.m16n8k8.row.col.f32.tf32.tf32.f32 "
        "{%0,%1,%2,%3}, {%4,%5,%6,%7}, {%8,%9}, {%0,%1,%2,%3};\n"
        : "+f"(acc[0]), "+f"(acc[1]), "+f"(acc[2]), "+f"(acc[3])
        : "r"(__float_as_uint(a0)), "r"(__float_as_uint(a1)),
          "r"(__float_as_uint(a2)), "r"(__float_as_uint(a3)),
          "r"(__float_as_uint(b0)), "r"(__float_as_uint(b1)));
}

// 16B async copy gmem -> smem, L2-only (streaming x).
__device__ __forceinline__ void cpa16(unsigned dst, const void* src) {
    asm volatile("cp.async.cg.shared.global [%0], [%1], 16;\n"
                 :: "r"(dst), "l"(src));
}

// ---------------------------------------------------------------------------
// Pass 1: tensor-core dot partials. One 512-thread block per k-chunk of 512:
// 16 warps x 16 b-rows = all 256 b -> m staged ONCE per chunk (halves m DRAM
// reads vs the 2-tile version). Proven KS=32 double-buffered cp.async per
// warp. No ||x|| (expert-invariant for the argmax).
// ---------------------------------------------------------------------------
__global__ void __launch_bounds__(512) k_dots(const float* __restrict__ x,
                                              const float* __restrict__ mem)
{
    extern __shared__ float smem_[];
    float* m_s = smem_;                        // 8 * 516 floats
    float* x_s = smem_ + 8 * MSTR;             // 16 warps * 2 * 576 floats

    const int c   = blockIdx.x;                // chunk
    const int tid = threadIdx.x;
    const int w   = tid >> 5;                  // 0..15
    const int l   = tid & 31;
    const int g   = l >> 2;                    // 0..7  (mma groupID)
    const int tg  = l & 3;                     // 0..3
    const int r0  = l >> 3;                    // 0..3  (staging row base)
    const int q   = l & 7;                     // 0..7  (staging quad col)

    const int b0row = w * 16;
    const float4* xb = (const float4*)x
                     + (size_t)(b0row + r0) * K4N + (size_t)c * CK4 + q;

    float* xw_base = x_s + w * (2 * XBUF);
    const unsigned xs_t = (unsigned)__cvta_generic_to_shared(xw_base)
                        + (unsigned)((r0 * XSTR + 4 * q) * 4);

    // ---- issue x slice-0 BEFORE m staging (overlap) ----
    #pragma unroll
    for (int i = 0; i < 4; ++i)
        cpa16(xs_t + (unsigned)(i * 4 * XSTR * 4), xb + (size_t)i * 4 * K4N);
    asm volatile("cp.async.commit_group;\n" ::: "memory");

    // ---- stage m chunk: 1024 float4 / 512 threads = 2 each (coalesced) ----
    const float4* m4 = (const float4*)mem;
    #pragma unroll
    for (int i = 0; i < 2; ++i) {
        int slot = tid + 512 * i;              // 0..1023
        int e = slot >> 7;                     // /128
        int qq = slot & 127;
        float4 v = m4[(size_t)e * K4N + (size_t)c * CK4 + qq];
        *(float4*)&m_s[e * MSTR + 4 * qq] = v;
    }
    __syncthreads();

    // ---- ||m_e||^2 chunk partials: warps 0..7 handle expert w ----
    if (w < 8) {
        float s = 0.f;
        #pragma unroll
        for (int j = 0; j < 4; ++j) {
            float4 f = *(const float4*)&m_s[w * MSTR + 4 * (l + 32 * j)];
            s += f.x * f.x + f.y * f.y + f.z * f.z + f.w * f.w;
        }
        s = warp_sum(s);
        if (l == 0) g_mpart[w * NCH + c] = s;
    }

    float acc[4] = {0.f, 0.f, 0.f, 0.f};

    #pragma unroll 1
    for (int s = 0; s < NSL; ++s) {
        if (s + 1 < NSL) {
            const unsigned nb = (unsigned)(((s + 1) & 1) * XBUF * 4);
            #pragma unroll
            for (int i = 0; i < 4; ++i)
                cpa16(xs_t + nb + (unsigned)(i * 4 * XSTR * 4),
                      xb + (size_t)i * 4 * K4N + (size_t)(s + 1) * 8);
            asm volatile("cp.async.commit_group;\n" ::: "memory");
            asm volatile("cp.async.wait_group 1;\n" ::: "memory");
        } else {
            asm volatile("cp.async.wait_group 0;\n" ::: "memory");
        }
        __syncwarp();

        const float* xw = xw_base + (s & 1) * XBUF;
        const int cbase = s * KS;
        #pragma unroll
        for (int k8 = 0; k8 < KS / 8; ++k8) {
            const int k = k8 * 8;
            // A fragments (row-major 16x8): rows g, g+8; cols k+tg, k+4+tg
            float a0 = xw[g       * XSTR + k + tg];
            float a1 = xw[(g + 8) * XSTR + k + tg];
            float a2 = xw[g       * XSTR + k + 4 + tg];
            float a3 = xw[(g + 8) * XSTR + k + 4 + tg];
            // B fragments (col-major 8x8): B[k][n] = m[n][k]; n = g
            float b0 = m_s[g * MSTR + cbase + k + tg];
            float b1 = m_s[g * MSTR + cbase + k + 4 + tg];

            mma_tf32(acc, a0, a1, a2, a3, b0, b1);
        }
        __syncwarp();   // all lanes done reading buffer s&1 before refill
    }

    // ---- write dot partials, layout [b][c][e]: 4 lanes of a g-group fill
    // one 32B sector per b with float2 stores -> zero sector amplification ----
    const size_t bl = ((size_t)(b0row + g)     * NCH + c) * EN;
    const size_t bh = ((size_t)(b0row + g + 8) * NCH + c) * EN;
    *(float2*)&g_dotp[bl + 2 * tg] = make_float2(acc[0], acc[1]);
    *(float2*)&g_dotp[bh + 2 * tg] = make_float2(acc[2], acc[3]);
}

// ---------------------------------------------------------------------------
// Pass 2: one block per b. g_dotp[b] is 64 KB CONTIGUOUS: thread tid reads
// elements tid, tid+256, ... (perfectly coalesced, accumulator owns fixed
// (c mod 32, e)). Deterministic fixed-order reductions.
// ---------------------------------------------------------------------------
__global__ void __launch_bounds__(256) k_argmax(float* __restrict__ outExp)
{
    const int b   = blockIdx.x;
    const int tid = threadIdx.x;
    const int w   = tid >> 5;
    const int l   = tid & 31;

    __shared__ float red[256];
    __shared__ float sdot[EN];
    __shared__ float smn[EN];

    // ---- dot accumulation: contiguous streaming, index = (c*8+e) ----
    {
        const float* p = g_dotp + (size_t)b * NCH * EN;
        float acc = 0.f;
        #pragma unroll 8
        for (int i = 0; i < NCH * EN / 256; ++i)    // 64 iterations
            acc += p[i * 256 + tid];
        red[tid] = acc;                             // red[(c%32)*8 + e]
    }
    // ---- ||m_e||^2: warp w reduces expert w's chunk partials ----
    {
        const float* p = g_mpart + (size_t)w * NCH;
        float v = 0.f;
        #pragma unroll
        for (int g = 0; g < NCH / 32; ++g) v += p[g * 32 + l];
        v = warp_sum(v);
        if (l == 0) smn[w] = v;
    }
    __syncthreads();

    if (tid < 8) {
        float v = 0.f;
        #pragma unroll
        for (int j = 0; j < 32; ++j) v += red[j * 8 + tid];
        sdot[tid] = v;
    }
    __syncthreads();

    if (tid == 0) {
        float best = -3.4e38f;
        int   bi   = 0;
        #pragma unroll
        for (int e = 0; e < EN; ++e) {
            float s = sdot[e] / sqrtf(smn[e]);
            if (s > best) { best = s; bi = e; }   // first-max (jnp.argmax)
        }
        g_experts[b] = bi;
        if (outExp) outExp[b] = (float)bi;
    }
}

// ---------------------------------------------------------------------------
// Pass 3: scatter-mean update with integrated ballot counting-sort prologue
// (every block recomputes the stable order from g_experts; deterministic).
// ---------------------------------------------------------------------------
__global__ void __launch_bounds__(256) k_update(const float* __restrict__ x,
                                                const float* __restrict__ mem,
                                                float* __restrict__ outMem)
{
    __shared__ int   s_order[BN];
    __shared__ int   s_offs[EN + 1];
    __shared__ float s_ka[EN];
    __shared__ float s_kb[EN];
    __shared__ int   wcnt[8][EN];

    const int tid = threadIdx.x;       // tid == b for the sort prologue
    const int w = tid >> 5, l = tid & 31;

    // ---- stable counting sort by expert (ballot ranking) ----
    if (tid < 8 * EN) ((int*)wcnt)[tid] = 0;
    __syncthreads();

    const int e = g_experts[tid];
    unsigned mk = __match_any_sync(0xffffffffu, e);
    int lower = __popc(mk & ((1u << l) - 1u));
    if (lower == 0) wcnt[w][e] = __popc(mk);
    __syncthreads();

    if (tid < EN) {
        int t = 0;
        #pragma unroll
        for (int ww = 0; ww < 8; ++ww) t += wcnt[ww][tid];
        s_offs[tid + 1] = t;
        if (t > 0) { s_ka[tid] = 0.5f; s_kb[tid] = 0.5f / (float)t; }
        else       { s_ka[tid] = 1.0f; s_kb[tid] = 0.0f; }
    }
    __syncthreads();
    if (tid == 0) {
        s_offs[0] = 0;
        #pragma unroll
        for (int i = 0; i < EN; ++i) s_offs[i + 1] += s_offs[i];
    }
    __syncthreads();

    {
        int rank = lower;
        #pragma unroll
        for (int ww = 0; ww < 8; ++ww)
            if (ww < w) rank += wcnt[ww][e];
        s_order[s_offs[e] + rank] = tid;
    }
    __syncthreads();

    // ---- streaming update ----
    const size_t j4 = (size_t)blockIdx.x * 256 + tid;
    const float4* x4 = (const float4*)x;
    const float4* m4 = (const float4*)mem;
    float4*       o4 = (float4*)outMem;

    #pragma unroll 1
    for (int ee = 0; ee < EN; ++ee) {
        float ax = 0.f, ay = 0.f, az = 0.f, aw = 0.f;
        const int lo = s_offs[ee];
        const int hi = s_offs[ee + 1];
        #pragma unroll 4
        for (int i = lo; i < hi; ++i) {
            int b = s_order[i];
            float4 f = x4[(size_t)b * K4N + j4];
            ax += f.x; ay += f.y; az += f.z; aw += f.w;
        }
        const float ka = s_ka[ee];
        const float kb = s_kb[ee];
        float4 mv = m4[(size_t)ee * K4N + j4];
        float4 ov;
        ov.x = ka * mv.x + kb * ax;
        ov.y = ka * mv.y + kb * ay;
        ov.z = ka * mv.z + kb * az;
        ov.w = ka * mv.w + kb * aw;
        o4[(size_t)ee * K4N + j4] = ov;
    }
}

// ---------------------------------------------------------------------------
extern "C" void kernel_launch(void* const* d_in, const int* in_sizes, int n_in,
                              void* d_out, int out_size)
{
    const float* x   = (const float*)d_in[0];
    const float* mem = (const float*)d_in[1];
    float* out = (float*)d_out;

    const long memElems = (long)EN * KN;          // 8388608
    float* outExp = nullptr;
    float* outMem = nullptr;
    if ((long)out_size == memElems + BN) {        // concat: experts then new_memory
        outExp = out;
        outMem = out + BN;
    } else if ((long)out_size == memElems) {      // new_memory only
        outMem = out;
    } else {                                      // experts only (fallback)
        outExp = out;
    }

    cudaFuncSetAttribute(k_dots, cudaFuncAttributeMaxDynamicSharedMemorySize, DSMEM);

    k_dots<<<NCH, 512, DSMEM>>>(x, mem);
    k_argmax<<<BN, 256>>>(outExp);
    if (outMem) k_update<<<K4N / 256, 256>>>(x, mem, outMem);
}